// round 1
// baseline (speedup 1.0000x reference)
#include <cuda_runtime.h>

// Problem constants (fixed by reference)
#define NB   2048
#define SRC  64
#define PAD  32
#define TH   128
#define TW   128
// padded input is 128x128; data region is [PAD, PAD+SRC) = [32, 96)

__global__ void __launch_bounds__(256, 6)
affine_sampler_kernel(const float* __restrict__ affine,   // (N,6)
                      const float* __restrict__ fill,     // (N,64,64)
                      const float* __restrict__ stroke,   // (N,64,64)
                      float* __restrict__ out_fill,       // (N,128,128)
                      float* __restrict__ out_stroke)     // (N,128,128)
{
    __shared__ float s_fill[SRC * SRC];     // 16 KB
    __shared__ float s_stroke[SRC * SRC];   // 16 KB

    const int n   = blockIdx.x;
    const int tid = threadIdx.x;

    // ---- stage source tiles into smem (float4, fully coalesced) ----
    {
        const float4* gf = (const float4*)(fill   + (size_t)n * SRC * SRC);
        const float4* gs = (const float4*)(stroke + (size_t)n * SRC * SRC);
        float4* sf = (float4*)s_fill;
        float4* ss = (float4*)s_stroke;
        // 4096 floats = 1024 float4 per tile; 256 threads -> 4 each
        #pragma unroll
        for (int i = 0; i < 4; i++) {
            sf[tid + i * 256] = gf[tid + i * 256];
            ss[tid + i * 256] = gs[tid + i * 256];
        }
    }

    // ---- theta (every thread computes; 6 broadcast loads, cheap) ----
    const float* a = affine + n * 6;
    const float a00 = 2.0f / (1.0f + __expf(-a[0]));
    const float a11 = 2.0f / (1.0f + __expf(-a[1]));
    const float a01 = 2.0f * tanhf(a[2]);
    const float a10 = 2.0f * tanhf(a[3]);
    const float a02 = tanhf(a[4]);
    const float a12 = tanhf(a[5]);

    __syncthreads();

    float* of = out_fill   + (size_t)n * TH * TW;
    float* os = out_stroke + (size_t)n * TH * TW;

    // Each thread produces 16 float4 vectors (64 pixels).
    // vector index vi in [0, 4096): y = vi/32, x0 = (vi%32)*4
    #pragma unroll 4
    for (int it = 0; it < 16; it++) {
        const int vi = tid + it * 256;
        const int y  = vi >> 5;
        const int xb = (vi & 31) << 2;

        const float Y = (y + 0.5f) * (2.0f / (float)TH) - 1.0f;

        float4 rf, rs;
        float* rfp = (float*)&rf;
        float* rsp = (float*)&rs;

        #pragma unroll
        for (int k = 0; k < 4; k++) {
            const int x = xb + k;
            const float X = (x + 0.5f) * (2.0f / (float)TW) - 1.0f;

            const float gx = a00 * X + a01 * Y + a02;
            const float gy = a10 * X + a11 * Y + a12;
            // ix = ((gx+1)*WIN - 1)*0.5 with WIN=128
            const float ix = ((gx + 1.0f) * 128.0f - 1.0f) * 0.5f;
            const float iy = ((gy + 1.0f) * 128.0f - 1.0f) * 0.5f;

            const float fx0 = floorf(ix);
            const float fy0 = floorf(iy);
            const float wx = ix - fx0;
            const float wy = iy - fy0;

            const int x0 = (int)fx0;
            const int y0 = (int)fy0;
            const int x1 = x0 + 1;
            const int y1 = y0 + 1;

            // a tap is nonzero iff padded coord in [32,96) both dims
            const bool vx0 = (x0 >= PAD) && (x0 < PAD + SRC);
            const bool vx1 = (x1 >= PAD) && (x1 < PAD + SRC);
            const bool vy0 = (y0 >= PAD) && (y0 < PAD + SRC);
            const bool vy1 = (y1 >= PAD) && (y1 < PAD + SRC);

            const int i00 = (y0 - PAD) * SRC + (x0 - PAD);
            const int i10 = (y0 - PAD) * SRC + (x1 - PAD);
            const int i01 = (y1 - PAD) * SRC + (x0 - PAD);
            const int i11 = (y1 - PAD) * SRC + (x1 - PAD);

            const float w00 = (1.0f - wx) * (1.0f - wy);
            const float w10 = wx * (1.0f - wy);
            const float w01 = (1.0f - wx) * wy;
            const float w11 = wx * wy;

            float fv = 0.0f, sv = 0.0f;
            if (vx0 & vy0) { fv += s_fill[i00] * w00; sv += s_stroke[i00] * w00; }
            if (vx1 & vy0) { fv += s_fill[i10] * w10; sv += s_stroke[i10] * w10; }
            if (vx0 & vy1) { fv += s_fill[i01] * w01; sv += s_stroke[i01] * w01; }
            if (vx1 & vy1) { fv += s_fill[i11] * w11; sv += s_stroke[i11] * w11; }

            rfp[k] = fv;
            rsp[k] = sv;
        }

        ((float4*)of)[vi] = rf;
        ((float4*)os)[vi] = rs;
    }
}

extern "C" void kernel_launch(void* const* d_in, const int* in_sizes, int n_in,
                              void* d_out, int out_size) {
    const float* affine = (const float*)d_in[0];   // (N,6) fp32
    const float* fill   = (const float*)d_in[1];   // (N,64,64) fp32
    const float* stroke = (const float*)d_in[2];   // (N,64,64) fp32
    // d_in[3] = targetsize (unused, constant SRC)

    float* out_fill   = (float*)d_out;
    float* out_stroke = (float*)d_out + (size_t)NB * TH * TW;

    affine_sampler_kernel<<<NB, 256>>>(affine, fill, stroke, out_fill, out_stroke);
}

// round 2
// speedup vs baseline: 1.1236x; 1.1236x over previous
#include <cuda_runtime.h>

#define NB   2048
#define SRC  64
#define PAD  32

// Interleaved smem tile: s[(y*64+x)*2 + 0] = fill, +1 = stroke. 32 KB exactly.
__global__ void __launch_bounds__(256, 6)
affine_sampler_kernel(const float* __restrict__ affine,   // (N,6)
                      const float* __restrict__ fill,     // (N,64,64)
                      const float* __restrict__ stroke,   // (N,64,64)
                      float* __restrict__ out_fill,       // (N,128,128)
                      float* __restrict__ out_stroke)     // (N,128,128)
{
    __shared__ float s[SRC * SRC * 2];   // 32 KB interleaved fill/stroke

    const int n   = blockIdx.x;
    const int tid = threadIdx.x;

    // ---- stage + interleave source tiles (float4 global reads, coalesced) ----
    {
        const float4* gf = (const float4*)(fill   + (size_t)n * SRC * SRC);
        const float4* gs = (const float4*)(stroke + (size_t)n * SRC * SRC);
        #pragma unroll
        for (int i = 0; i < 4; i++) {
            const int v = tid + i * 256;          // float4 index 0..1023
            float4 f  = gf[v];
            float4 st = gs[v];
            float2* dst = (float2*)&s[v * 8];
            dst[0] = make_float2(f.x, st.x);
            dst[1] = make_float2(f.y, st.y);
            dst[2] = make_float2(f.z, st.z);
            dst[3] = make_float2(f.w, st.w);
        }
    }

    // ---- theta (broadcast loads; every thread computes) ----
    const float* a = affine + n * 6;
    const float a00 = 2.0f / (1.0f + __expf(-a[0]));
    const float a11 = 2.0f / (1.0f + __expf(-a[1]));
    const float a01 = 2.0f * tanhf(a[2]);
    const float a10 = 2.0f * tanhf(a[3]);
    const float a02 = tanhf(a[4]);
    const float a12 = tanhf(a[5]);

    // Fold normalized-coord chain:  ix = a00*x + a01*y + Cx  (pixel coords in padded img)
    const float Cx = 64.0f * a02 + 63.5f - 63.5f * (a00 + a01);
    const float Cy = 64.0f * a12 + 63.5f - 63.5f * (a10 + a11);

    __syncthreads();

    float* of = out_fill   + (size_t)n * 128 * 128;
    float* os = out_stroke + (size_t)n * 128 * 128;

    const int lane = tid & 31;
    const int warp = tid >> 5;
    const float xf = (float)(lane << 2);   // 4 contiguous pixels per lane

    #pragma unroll 2
    for (int it = 0; it < 16; it++) {
        const int   row = it * 8 + warp;
        const float yf  = (float)row;

        float ix = fmaf(a00, xf, fmaf(a01, yf, Cx));
        float iy = fmaf(a10, xf, fmaf(a11, yf, Cy));

        float4 rf, rs;
        float* rfp = &rf.x;
        float* rsp = &rs.x;

        #pragma unroll
        for (int k = 0; k < 4; k++) {
            const int x0 = __float2int_rd(ix);
            const int y0 = __float2int_rd(iy);
            const float wx = ix - (float)x0;
            const float wy = iy - (float)y0;
            const float mx = 1.0f - wx;
            const float my = 1.0f - wy;

            // tap validity in padded coords: data region [32, 96)
            const bool vx0 = (unsigned)(x0 - PAD)     < 64u;
            const bool vx1 = (unsigned)(x0 - PAD + 1) < 64u;
            const bool vy0 = (unsigned)(y0 - PAD)     < 64u;
            const bool vy1 = (unsigned)(y0 - PAD + 1) < 64u;

            const int base = ((y0 - PAD) * SRC + (x0 - PAD)) * 2;

            float fv = 0.0f, sv = 0.0f;
            if (vx0 & vy0) { float2 r = *(const float2*)&s[base];       float w = mx * my; fv = fmaf(r.x, w, fv); sv = fmaf(r.y, w, sv); }
            if (vx1 & vy0) { float2 r = *(const float2*)&s[base + 2];   float w = wx * my; fv = fmaf(r.x, w, fv); sv = fmaf(r.y, w, sv); }
            if (vx0 & vy1) { float2 r = *(const float2*)&s[base + 128]; float w = mx * wy; fv = fmaf(r.x, w, fv); sv = fmaf(r.y, w, sv); }
            if (vx1 & vy1) { float2 r = *(const float2*)&s[base + 130]; float w = wx * wy; fv = fmaf(r.x, w, fv); sv = fmaf(r.y, w, sv); }

            rfp[k] = fv;
            rsp[k] = sv;

            ix += a00;
            iy += a10;
        }

        const int o = row * 128 + (lane << 2);
        *(float4*)&of[o] = rf;
        *(float4*)&os[o] = rs;
    }
}

extern "C" void kernel_launch(void* const* d_in, const int* in_sizes, int n_in,
                              void* d_out, int out_size) {
    const float* affine = (const float*)d_in[0];   // (N,6) fp32
    const float* fill   = (const float*)d_in[1];   // (N,64,64) fp32
    const float* stroke = (const float*)d_in[2];   // (N,64,64) fp32
    // d_in[3] = targetsize (constant, unused)

    float* out_fill   = (float*)d_out;
    float* out_stroke = (float*)d_out + (size_t)NB * 128 * 128;

    affine_sampler_kernel<<<NB, 256>>>(affine, fill, stroke, out_fill, out_stroke);
}

// round 3
// speedup vs baseline: 1.2443x; 1.1074x over previous
#include <cuda_runtime.h>

#define NB   2048
#define SRC  64
#define PAD  32

// Interleaved smem tile: s[(y*64+x)*2 + 0] = fill, +1 = stroke. 32 KB.
__global__ void __launch_bounds__(256, 6)
affine_sampler_kernel(const float* __restrict__ affine,   // (N,6)
                      const float* __restrict__ fill,     // (N,64,64)
                      const float* __restrict__ stroke,   // (N,64,64)
                      float* __restrict__ out_fill,       // (N,128,128)
                      float* __restrict__ out_stroke)     // (N,128,128)
{
    __shared__ float s[SRC * SRC * 2];   // 32 KB interleaved fill/stroke

    const int n   = blockIdx.x;
    const int tid = threadIdx.x;

    // ---- stage + interleave source tiles (float4 global reads, coalesced) ----
    {
        const float4* gf = (const float4*)(fill   + (size_t)n * SRC * SRC);
        const float4* gs = (const float4*)(stroke + (size_t)n * SRC * SRC);
        #pragma unroll
        for (int i = 0; i < 4; i++) {
            const int v = tid + i * 256;          // float4 index 0..1023
            float4 f  = gf[v];
            float4 st = gs[v];
            float2* dst = (float2*)&s[v * 8];
            dst[0] = make_float2(f.x, st.x);
            dst[1] = make_float2(f.y, st.y);
            dst[2] = make_float2(f.z, st.z);
            dst[3] = make_float2(f.w, st.w);
        }
    }

    // ---- theta (broadcast loads; every thread computes) ----
    const float* a = affine + n * 6;
    const float a00 = 2.0f / (1.0f + __expf(-a[0]));
    const float a11 = 2.0f / (1.0f + __expf(-a[1]));
    const float a01 = 2.0f * tanhf(a[2]);
    const float a10 = 2.0f * tanhf(a[3]);
    const float a02 = tanhf(a[4]);
    const float a12 = tanhf(a[5]);

    // Folded chain: ix = a00*x + a01*y + Cx  (pixel coords in padded 128x128 img)
    const float Cx = 64.0f * a02 + 63.5f - 63.5f * (a00 + a01);
    const float Cy = 64.0f * a12 + 63.5f - 63.5f * (a10 + a11);

    __syncthreads();

    float* of = out_fill   + (size_t)n * 128 * 128;
    float* os = out_stroke + (size_t)n * 128 * 128;

    const int lane = tid & 31;
    const int warp = tid >> 5;
    const float xf = (float)(lane << 2);   // 4 contiguous pixels per lane
    const float dx3 = 3.0f * a00;          // a00 > 0 always
    const float dy3 = 3.0f * a10;          // sign unknown

    #pragma unroll 1
    for (int it = 0; it < 16; it++) {
        const int   row = it * 8 + warp;
        const float yf  = (float)row;

        float ix = fmaf(a00, xf, fmaf(a01, yf, Cx));
        float iy = fmaf(a10, xf, fmaf(a11, yf, Cy));

        // group coordinate bounds (coords monotonic in k)
        const float lox = ix,  hix = ix + dx3;
        const float loy = fminf(iy, iy + dy3);
        const float hiy = fmaxf(iy, iy + dy3);

        // all 16 taps of this 4-pixel group valid?
        const bool inside = (lox >= 32.0f) & (hix < 95.0f) &
                            (loy >= 32.0f) & (hiy < 95.0f);
        // all 4 pixels exactly zero? (pixel nonzero needs ix in [31,96) AND iy in [31,96))
        const bool zero = (hix < 31.0f) | (lox >= 96.0f) |
                          (hiy < 31.0f) | (loy >= 96.0f);

        const int o = row * 128 + (lane << 2);
        const unsigned bal_in = __ballot_sync(0xffffffffu, inside);

        float4 rf, rs;
        float* rfp = &rf.x;
        float* rsp = &rs.x;

        if (bal_in == 0xffffffffu) {
            // ---- fast interior path: no bounds checks, no predication ----
            #pragma unroll
            for (int k = 0; k < 4; k++) {
                const int x0 = __float2int_rd(ix);
                const int y0 = __float2int_rd(iy);
                const float wx = ix - (float)x0;
                const float wy = iy - (float)y0;
                const float mx = 1.0f - wx;
                const float my = 1.0f - wy;

                const int base = ((y0 - PAD) * SRC + (x0 - PAD)) * 2;
                const float2 r00 = *(const float2*)&s[base];
                const float2 r10 = *(const float2*)&s[base + 2];
                const float2 r01 = *(const float2*)&s[base + 128];
                const float2 r11 = *(const float2*)&s[base + 130];

                const float w00 = mx * my, w10 = wx * my;
                const float w01 = mx * wy, w11 = wx * wy;

                float fv = r00.x * w00, sv = r00.y * w00;
                fv = fmaf(r10.x, w10, fv); sv = fmaf(r10.y, w10, sv);
                fv = fmaf(r01.x, w01, fv); sv = fmaf(r01.y, w01, sv);
                fv = fmaf(r11.x, w11, fv); sv = fmaf(r11.y, w11, sv);

                rfp[k] = fv;
                rsp[k] = sv;
                ix += a00;
                iy += a10;
            }
            __stcs((float4*)&of[o], rf);
            __stcs((float4*)&os[o], rs);
        } else if (__ballot_sync(0xffffffffu, zero) == 0xffffffffu) {
            // ---- all-zero warp: just store zeros ----
            const float4 z = make_float4(0.f, 0.f, 0.f, 0.f);
            __stcs((float4*)&of[o], z);
            __stcs((float4*)&os[o], z);
        } else {
            // ---- generic boundary path (predicated taps) ----
            #pragma unroll
            for (int k = 0; k < 4; k++) {
                const int x0 = __float2int_rd(ix);
                const int y0 = __float2int_rd(iy);
                const float wx = ix - (float)x0;
                const float wy = iy - (float)y0;
                const float mx = 1.0f - wx;
                const float my = 1.0f - wy;

                const bool vx0 = (unsigned)(x0 - PAD)     < 64u;
                const bool vx1 = (unsigned)(x0 - PAD + 1) < 64u;
                const bool vy0 = (unsigned)(y0 - PAD)     < 64u;
                const bool vy1 = (unsigned)(y0 - PAD + 1) < 64u;

                const int base = ((y0 - PAD) * SRC + (x0 - PAD)) * 2;

                float fv = 0.0f, sv = 0.0f;
                if (vx0 & vy0) { float2 r = *(const float2*)&s[base];       float w = mx * my; fv = fmaf(r.x, w, fv); sv = fmaf(r.y, w, sv); }
                if (vx1 & vy0) { float2 r = *(const float2*)&s[base + 2];   float w = wx * my; fv = fmaf(r.x, w, fv); sv = fmaf(r.y, w, sv); }
                if (vx0 & vy1) { float2 r = *(const float2*)&s[base + 128]; float w = mx * wy; fv = fmaf(r.x, w, fv); sv = fmaf(r.y, w, sv); }
                if (vx1 & vy1) { float2 r = *(const float2*)&s[base + 130]; float w = wx * wy; fv = fmaf(r.x, w, fv); sv = fmaf(r.y, w, sv); }

                rfp[k] = fv;
                rsp[k] = sv;
                ix += a00;
                iy += a10;
            }
            __stcs((float4*)&of[o], rf);
            __stcs((float4*)&os[o], rs);
        }
    }
}

extern "C" void kernel_launch(void* const* d_in, const int* in_sizes, int n_in,
                              void* d_out, int out_size) {
    const float* affine = (const float*)d_in[0];   // (N,6) fp32
    const float* fill   = (const float*)d_in[1];   // (N,64,64) fp32
    const float* stroke = (const float*)d_in[2];   // (N,64,64) fp32
    // d_in[3] = targetsize (constant, unused)

    float* out_fill   = (float*)d_out;
    float* out_stroke = (float*)d_out + (size_t)NB * 128 * 128;

    affine_sampler_kernel<<<NB, 256>>>(affine, fill, stroke, out_fill, out_stroke);
}

// round 4
// speedup vs baseline: 1.2673x; 1.0185x over previous
#include <cuda_runtime.h>

#define NB   2048
#define SRC  64
#define PAD  32

// Interleaved smem tile: s[(y*64+x)*2 + 0] = fill, +1 = stroke. 32 KB.
__global__ void __launch_bounds__(512, 4)
affine_sampler_kernel(const float* __restrict__ affine,   // (N,6)
                      const float* __restrict__ fill,     // (N,64,64)
                      const float* __restrict__ stroke,   // (N,64,64)
                      float* __restrict__ out_fill,       // (N,128,128)
                      float* __restrict__ out_stroke)     // (N,128,128)
{
    __shared__ float s[SRC * SRC * 2];   // 32 KB interleaved fill/stroke

    const int n   = blockIdx.x;
    const int tid = threadIdx.x;

    // ---- stage + interleave source tiles (float4 global reads, coalesced) ----
    {
        const float4* gf = (const float4*)(fill   + (size_t)n * SRC * SRC);
        const float4* gs = (const float4*)(stroke + (size_t)n * SRC * SRC);
        #pragma unroll
        for (int i = 0; i < 2; i++) {
            const int v = tid + i * 512;          // float4 index 0..1023
            float4 f  = gf[v];
            float4 st = gs[v];
            float2* dst = (float2*)&s[v * 8];
            dst[0] = make_float2(f.x, st.x);
            dst[1] = make_float2(f.y, st.y);
            dst[2] = make_float2(f.z, st.z);
            dst[3] = make_float2(f.w, st.w);
        }
    }

    // ---- theta (broadcast loads; every thread computes) ----
    const float* a = affine + n * 6;
    const float a00 = 2.0f / (1.0f + __expf(-a[0]));
    const float a11 = 2.0f / (1.0f + __expf(-a[1]));
    const float a01 = 2.0f * tanhf(a[2]);
    const float a10 = 2.0f * tanhf(a[3]);
    const float a02 = tanhf(a[4]);
    const float a12 = tanhf(a[5]);

    // Folded chain: ix = a00*x + a01*y + Cx  (pixel coords in padded 128x128 img)
    const float Cx = 64.0f * a02 + 63.5f - 63.5f * (a00 + a01);
    const float Cy = 64.0f * a12 + 63.5f - 63.5f * (a10 + a11);

    __syncthreads();

    float* of = out_fill   + (size_t)n * 128 * 128;
    float* os = out_stroke + (size_t)n * 128 * 128;

    const int lane = tid & 31;
    const int warp = tid >> 5;              // 0..15
    const float xf = (float)(lane << 2);    // 4 contiguous pixels per lane
    const float dx3 = 3.0f * a00;           // a00 > 0 always
    const float dy3 = 3.0f * a10;           // sign unknown

    #pragma unroll 1
    for (int it = 0; it < 8; it++) {
        const int   row = it * 16 + warp;
        const float yf  = (float)row;

        float ix = fmaf(a00, xf, fmaf(a01, yf, Cx));
        float iy = fmaf(a10, xf, fmaf(a11, yf, Cy));

        // group coordinate bounds (coords monotonic in k)
        const float lox = ix,  hix = ix + dx3;
        const float loy = fminf(iy, iy + dy3);
        const float hiy = fmaxf(iy, iy + dy3);

        // all 16 taps of this 4-pixel group valid?
        const bool inside = (lox >= 32.0f) & (hix < 95.0f) &
                            (loy >= 32.0f) & (hiy < 95.0f);
        // all 4 pixels exactly zero? (pixel nonzero needs ix,iy in [31,96))
        const bool zero = (hix < 31.0f) | (lox >= 96.0f) |
                          (hiy < 31.0f) | (loy >= 96.0f);

        const int o = row * 128 + (lane << 2);
        const unsigned bal_in = __ballot_sync(0xffffffffu, inside);

        float4 rf, rs;
        float* rfp = &rf.x;
        float* rsp = &rs.x;

        if (bal_in == 0xffffffffu) {
            // ---- fast interior path: no bounds checks, no predication ----
            #pragma unroll
            for (int k = 0; k < 4; k++) {
                const float fx0 = floorf(ix);
                const float fy0 = floorf(iy);
                const float wx = ix - fx0;
                const float wy = iy - fy0;
                const float mx = 1.0f - wx;
                const float my = 1.0f - wy;

                // (y0-32)*64 + (x0-32) in float2 units = fy0*64+fx0 - 2080
                // exact: integers <= 6112 < 2^24; single F2I, no IMAD
                const int base = (__float2int_rn(fmaf(fy0, 64.0f, fx0)) - 2080) * 2;
                const float2 r00 = *(const float2*)&s[base];
                const float2 r10 = *(const float2*)&s[base + 2];
                const float2 r01 = *(const float2*)&s[base + 128];
                const float2 r11 = *(const float2*)&s[base + 130];

                const float w00 = mx * my, w10 = wx * my;
                const float w01 = mx * wy, w11 = wx * wy;

                float fv = r00.x * w00, sv = r00.y * w00;
                fv = fmaf(r10.x, w10, fv); sv = fmaf(r10.y, w10, sv);
                fv = fmaf(r01.x, w01, fv); sv = fmaf(r01.y, w01, sv);
                fv = fmaf(r11.x, w11, fv); sv = fmaf(r11.y, w11, sv);

                rfp[k] = fv;
                rsp[k] = sv;
                ix += a00;
                iy += a10;
            }
            __stcs((float4*)&of[o], rf);
            __stcs((float4*)&os[o], rs);
        } else if (__ballot_sync(0xffffffffu, zero) == 0xffffffffu) {
            // ---- all-zero warp: just store zeros ----
            const float4 z = make_float4(0.f, 0.f, 0.f, 0.f);
            __stcs((float4*)&of[o], z);
            __stcs((float4*)&os[o], z);
        } else {
            // ---- generic boundary path (predicated taps) ----
            #pragma unroll
            for (int k = 0; k < 4; k++) {
                const int x0 = __float2int_rd(ix);
                const int y0 = __float2int_rd(iy);
                const float wx = ix - (float)x0;
                const float wy = iy - (float)y0;
                const float mx = 1.0f - wx;
                const float my = 1.0f - wy;

                const bool vx0 = (unsigned)(x0 - PAD)     < 64u;
                const bool vx1 = (unsigned)(x0 - PAD + 1) < 64u;
                const bool vy0 = (unsigned)(y0 - PAD)     < 64u;
                const bool vy1 = (unsigned)(y0 - PAD + 1) < 64u;

                const int base = ((y0 - PAD) * SRC + (x0 - PAD)) * 2;

                float fv = 0.0f, sv = 0.0f;
                if (vx0 & vy0) { float2 r = *(const float2*)&s[base];       float w = mx * my; fv = fmaf(r.x, w, fv); sv = fmaf(r.y, w, sv); }
                if (vx1 & vy0) { float2 r = *(const float2*)&s[base + 2];   float w = wx * my; fv = fmaf(r.x, w, fv); sv = fmaf(r.y, w, sv); }
                if (vx0 & vy1) { float2 r = *(const float2*)&s[base + 128]; float w = mx * wy; fv = fmaf(r.x, w, fv); sv = fmaf(r.y, w, sv); }
                if (vx1 & vy1) { float2 r = *(const float2*)&s[base + 130]; float w = wx * wy; fv = fmaf(r.x, w, fv); sv = fmaf(r.y, w, sv); }

                rfp[k] = fv;
                rsp[k] = sv;
                ix += a00;
                iy += a10;
            }
            __stcs((float4*)&of[o], rf);
            __stcs((float4*)&os[o], rs);
        }
    }
}

extern "C" void kernel_launch(void* const* d_in, const int* in_sizes, int n_in,
                              void* d_out, int out_size) {
    const float* affine = (const float*)d_in[0];   // (N,6) fp32
    const float* fill   = (const float*)d_in[1];   // (N,64,64) fp32
    const float* stroke = (const float*)d_in[2];   // (N,64,64) fp32
    // d_in[3] = targetsize (constant, unused)

    float* out_fill   = (float*)d_out;
    float* out_stroke = (float*)d_out + (size_t)NB * 128 * 128;

    affine_sampler_kernel<<<NB, 512>>>(affine, fill, stroke, out_fill, out_stroke);
}